// round 14
// baseline (speedup 1.0000x reference)
#include <cuda_runtime.h>
#include <cstdint>

// FullAttention causal MHA, B=2, L=2048, H=16, E=D=64, fp32.
// R14: cp.async triple-buffered K/V pipeline (R13) + in-smem RNA fixup:
//   tf32 round-to-nearest == (f32 bits + 0x1000) then HW truncation in mma.
//   After each tile lands, a strided LDS.128/IADD/STS.128 pass adds 0x1000 to
//   every word (carry into exponent = correct round-up; sign-magnitude = RNA).
//   Restores R12 accuracy (~5.4e-4) while keeping GMEM latency fully hidden.
//   Two syncs/tile: [wait, sync, issue j+2, fixup j, sync, compute j].
//   Q staging region aliased with ring -> 105KB/CTA, 2 CTAs/SM.

#define B_   2
#define L_   2048
#define H_   16
#define E_   64
#define BM   128
#define BN   64
#define NTH  256
#define QSTR 68                      // K rows stride (floats); also Q staging
#define VSTR 72                      // V rows stride (floats)
#define KBYTES (BN * QSTR * 4)       // 17408
#define VBYTES (BN * VSTR * 4)       // 18432
#define BUFB   (KBYTES + VBYTES)     // 35840 per stage
#define SMEM_TOTAL (3 * BUFB)        // 107520 >= Q staging 34816

__device__ __forceinline__ float neg_inf() { return __int_as_float(0xff800000u); }

__device__ __forceinline__ uint32_t smem_u32(const void* p) {
    uint32_t a;
    asm("{ .reg .u64 t; cvta.to.shared.u64 t, %1; cvt.u32.u64 %0, t; }" : "=r"(a) : "l"(p));
    return a;
}
__device__ __forceinline__ uint32_t f2tf32(float x) {
    uint32_t r;
    asm("cvt.rna.tf32.f32 %0, %1;" : "=r"(r) : "f"(x));
    return r;
}
__device__ __forceinline__ float ex2(float x) {
    float y;
    asm("ex2.approx.f32 %0, %1;" : "=f"(y) : "f"(x));
    return y;
}
#define CP_ASYNC16(dst, src) \
    asm volatile("cp.async.cg.shared.global [%0], [%1], 16;" :: "r"(dst), "l"(src))
#define CP_COMMIT() asm volatile("cp.async.commit_group;" ::: "memory")
#define CP_WAIT1()  asm volatile("cp.async.wait_group 1;" ::: "memory")

// D = A(16x8 tf32) * B(8x8 tf32) + C, row.col, fp32 acc. d may alias c.
__device__ __forceinline__ void mma8(float* d, const uint32_t* a,
                                     uint32_t b0, uint32_t b1, const float* c) {
    asm volatile(
        "mma.sync.aligned.m16n8k8.row.col.f32.tf32.tf32.f32 "
        "{%0,%1,%2,%3}, {%4,%5,%6,%7}, {%8,%9}, {%10,%11,%12,%13};"
        : "=f"(d[0]), "=f"(d[1]), "=f"(d[2]), "=f"(d[3])
        : "r"(a[0]), "r"(a[1]), "r"(a[2]), "r"(a[3]),
          "r"(b0), "r"(b1),
          "f"(c[0]), "f"(c[1]), "f"(c[2]), "f"(c[3]));
}

__global__ __launch_bounds__(NTH, 2) void fa_mma_kernel(
    const float* __restrict__ Q, const float* __restrict__ K,
    const float* __restrict__ V, float* __restrict__ O)
{
    extern __shared__ char smem[];
    float* Qs = (float*)smem;              // Q staging (dead after preload)
    const uint32_t smb = smem_u32(smem);

    const int tid  = threadIdx.x;
    const int wid  = tid >> 5;
    const int lane = tid & 31;
    const int q4   = lane & 3;
    const int lr   = lane >> 2;
    const int r0   = (wid << 4) + lr;

    const int qtile = (int)gridDim.x - 1 - (int)blockIdx.x;   // longest first
    const int bh    = blockIdx.y;
    const int b     = bh >> 4;
    const int h     = bh & 15;
    const int m0    = qtile * BM;
    const int ntiles = 2 * (qtile + 1);

    const float scale2 = 0.125f * 1.4426950408889634f;  // 1/sqrt(64)*log2(e)

    // ---- stage Q (scaled, cvt.rna tf32), preload fragments ----
    {
        const int m  = tid >> 1;
        const int e0 = (tid & 1) * 32;
        const float* qg = Q + (((size_t)b * L_ + (m0 + m)) * H_ + h) * E_ + e0;
        #pragma unroll
        for (int i = 0; i < 8; ++i) {
            float4 v = *(const float4*)(qg + i * 4);
            uint4 t;
            t.x = f2tf32(v.x * scale2); t.y = f2tf32(v.y * scale2);
            t.z = f2tf32(v.z * scale2); t.w = f2tf32(v.w * scale2);
            *(uint4*)(Qs + m * QSTR + e0 + i * 4) = t;
        }
    }
    __syncthreads();

    uint32_t qf[8][4];
    {
        const uint32_t* Qu = (const uint32_t*)Qs;
        #pragma unroll
        for (int kt = 0; kt < 8; ++kt) {
            qf[kt][0] = Qu[ r0      * QSTR + 8 * kt + q4    ];
            qf[kt][1] = Qu[(r0 + 8) * QSTR + 8 * kt + q4    ];
            qf[kt][2] = Qu[ r0      * QSTR + 8 * kt + q4 + 4];
            qf[kt][3] = Qu[(r0 + 8) * QSTR + 8 * kt + q4 + 4];
        }
    }
    __syncthreads();   // Q region free: ring buffers may now be written

    // ---- cp.async loader geometry ----
    const int ln  = tid >> 2;              // 0..63 tile row
    const int le0 = (tid & 3) * 16;        // col base (floats)
    const float* kRow = K + (((size_t)b * L_ + ln) * H_ + h) * E_ + le0;
    const float* vRow = V + (((size_t)b * L_ + ln) * H_ + h) * E_ + le0;
    const size_t tstep = (size_t)BN * H_ * E_;
    const uint32_t kdst0 = smb + (uint32_t)(ln * QSTR + le0) * 4u;
    const uint32_t vdst0 = smb + KBYTES + (uint32_t)(ln * VSTR + le0) * 4u;

    #define ISSUE_TILE(t)                                                   \
        do {                                                                \
            if ((t) < ntiles) {                                             \
                const uint32_t boff = (uint32_t)((t) % 3) * BUFB;           \
                const float* kg = kRow + (size_t)(t) * tstep;               \
                const float* vg = vRow + (size_t)(t) * tstep;               \
                _Pragma("unroll")                                           \
                for (int i_ = 0; i_ < 4; ++i_) {                            \
                    CP_ASYNC16(kdst0 + boff + 16u * i_, kg + 4 * i_);       \
                    CP_ASYNC16(vdst0 + boff + 16u * i_, vg + 4 * i_);       \
                }                                                           \
            }                                                               \
            CP_COMMIT();                                                    \
        } while (0)

    ISSUE_TILE(0);
    ISSUE_TILE(1);

    float o[8][4];
    #pragma unroll
    for (int nt = 0; nt < 8; ++nt)
        #pragma unroll
        for (int u = 0; u < 4; ++u) o[nt][u] = 0.0f;
    float l0 = 0.0f, l1 = 0.0f;

    const int rowg0 = m0 + r0;
    const int rowg1 = rowg0 + 8;
    const int wrlast = m0 + (wid << 4) + 15;   // warp's last q-row

    for (int j = 0; j < ntiles; ++j) {
        const int n0 = j * BN;
        CP_WAIT1();
        __syncthreads();
        ISSUE_TILE(j + 2);      // buf (j+2)%3: consumed at j-1, sync-protected

        // ---- in-smem RNA fixup of buffer j: bits += 0x1000 ----
        {
            uint4* bw = (uint4*)(smem + (j % 3) * BUFB);
            #pragma unroll
            for (int i = tid; i < BUFB / 16; i += NTH) {
                uint4 w = bw[i];
                w.x += 0x1000u; w.y += 0x1000u; w.z += 0x1000u; w.w += 0x1000u;
                bw[i] = w;
            }
        }
        __syncthreads();

        if (n0 > wrlast) continue;   // whole warp causally masked this tile

        const char* buf = smem + (j % 3) * BUFB;
        const uint32_t* Ku = (const uint32_t*)buf;
        const uint32_t* Vu = (const uint32_t*)(buf + KBYTES);

        // ---- S = Q K^T ----
        float s[8][4];
        #pragma unroll
        for (int nt = 0; nt < 8; ++nt)
            #pragma unroll
            for (int u = 0; u < 4; ++u) s[nt][u] = 0.0f;

        #pragma unroll
        for (int kt = 0; kt < 8; ++kt) {
            #pragma unroll
            for (int nt = 0; nt < 8; ++nt) {
                uint32_t b0 = Ku[(8 * nt + lr) * QSTR + 8 * kt + q4];
                uint32_t b1 = Ku[(8 * nt + lr) * QSTR + 8 * kt + q4 + 4];
                mma8(s[nt], qf[kt], b0, b1, s[nt]);
            }
        }

        // ---- causal mask (two diagonal-adjacent tiles only) ----
        if (j >= ntiles - 2) {
            #pragma unroll
            for (int nt = 0; nt < 8; ++nt) {
                #pragma unroll
                for (int u = 0; u < 2; ++u) {
                    int colg = n0 + 8 * nt + 2 * q4 + u;
                    if (colg > rowg0) s[nt][u]     = neg_inf();
                    if (colg > rowg1) s[nt][2 + u] = neg_inf();
                }
            }
        }

        // ---- p = exp2(s); thread-local l ----
        #pragma unroll
        for (int nt = 0; nt < 8; ++nt) {
            float p0 = ex2(s[nt][0]);
            float p1 = ex2(s[nt][1]);
            float p2 = ex2(s[nt][2]);
            float p3 = ex2(s[nt][3]);
            s[nt][0] = p0; s[nt][1] = p1; s[nt][2] = p2; s[nt][3] = p3;
            l0 += p0 + p1;
            l1 += p2 + p3;
        }

        // ---- O += P V ----
        const int src_lo = (lane & ~3) | (q4 >> 1);
        const int src_hi = src_lo + 2;
        const bool odd = (q4 & 1);
        #pragma unroll
        for (int kt = 0; kt < 8; ++kt) {
            float va, vb;
            uint32_t a[4];
            va = __shfl_sync(0xffffffffu, s[kt][0], src_lo);
            vb = __shfl_sync(0xffffffffu, s[kt][1], src_lo);
            a[0] = __float_as_uint(odd ? vb : va);
            va = __shfl_sync(0xffffffffu, s[kt][2], src_lo);
            vb = __shfl_sync(0xffffffffu, s[kt][3], src_lo);
            a[1] = __float_as_uint(odd ? vb : va);
            va = __shfl_sync(0xffffffffu, s[kt][0], src_hi);
            vb = __shfl_sync(0xffffffffu, s[kt][1], src_hi);
            a[2] = __float_as_uint(odd ? vb : va);
            va = __shfl_sync(0xffffffffu, s[kt][2], src_hi);
            vb = __shfl_sync(0xffffffffu, s[kt][3], src_hi);
            a[3] = __float_as_uint(odd ? vb : va);

            #pragma unroll
            for (int nt = 0; nt < 8; ++nt) {
                uint32_t b0 = Vu[(8 * kt + q4    ) * VSTR + 8 * nt + lr];
                uint32_t b1 = Vu[(8 * kt + q4 + 4) * VSTR + 8 * nt + lr];
                mma8(o[nt], a, b0, b1, o[nt]);
            }
        }
    }

    // ---- epilogue: reduce l over quad, normalize, store ----
    {
        #pragma unroll
        for (int off = 1; off < 4; off <<= 1) {
            l0 += __shfl_xor_sync(0xffffffffu, l0, off);
            l1 += __shfl_xor_sync(0xffffffffu, l1, off);
        }
        float inv0 = 1.0f / l0, inv1 = 1.0f / l1;
        float* og0 = O + (((size_t)b * L_ + rowg0) * H_ + h) * E_;
        float* og1 = O + (((size_t)b * L_ + rowg1) * H_ + h) * E_;
        #pragma unroll
        for (int nt = 0; nt < 8; ++nt) {
            int col = 8 * nt + 2 * q4;
            *(float2*)(og0 + col) = make_float2(o[nt][0] * inv0, o[nt][1] * inv0);
            *(float2*)(og1 + col) = make_float2(o[nt][2] * inv1, o[nt][3] * inv1);
        }
    }
}

extern "C" void kernel_launch(void* const* d_in, const int* in_sizes, int n_in,
                              void* d_out, int out_size)
{
    const float* Q = (const float*)d_in[0];
    const float* K = (const float*)d_in[1];
    const float* V = (const float*)d_in[2];
    float* O = (float*)d_out;

    cudaFuncSetAttribute(fa_mma_kernel, cudaFuncAttributeMaxDynamicSharedMemorySize,
                         SMEM_TOTAL);
    dim3 grid(L_ / BM, B_ * H_);
    fa_mma_kernel<<<grid, NTH, SMEM_TOTAL>>>(Q, K, V, O);
}